// round 4
// baseline (speedup 1.0000x reference)
#include <cuda_runtime.h>
#include <cuda_fp16.h>
#include <cstdint>

#define N_NEURON 4096
#define N_BATCH  32
#define N_STEPS  300

// ---------------- device scratch (allocation-free rule: __device__ globals) ----
// W packed in per-lane MMA B-fragment layout, per 32-col tile:
//   entry (jt, kb, lane) = 16 halves (32 B):
//   halves[nb*4 + {0,1,2,3}] = W[k][j] for k = kb*16+(lane&3)*2 + {0,1,8,9},
//                                          j = jt*32 + nb*8 + (lane>>2)
__device__ __align__(256) __half g_W16[(size_t)N_NEURON * N_NEURON];
// rates in per-lane MMA A-fragment layout (ping-pong):
//   entry (kb, rb, lane) = 8 halves (16 B) = a0..a3 of m16k16 fragment
__device__ __align__(256) __half g_r16[2][N_BATCH * N_NEURON];
__device__ float g_rates[N_BATCH * N_NEURON];
__device__ float g_rec[N_BATCH * N_NEURON];
__device__ float g_acc[N_BATCH * N_NEURON];

// ---------------- W fp32 -> fp16 fragment pack (once per replay) --------------
__global__ void convert_w(const float* __restrict__ W) {
    int idx = blockIdx.x * blockDim.x + threadIdx.x;
    if (idx >= 128 * 256 * 32) return;
    int lane = idx & 31;
    int kb   = (idx >> 5) & 255;
    int jt   = idx >> 13;
    int k0   = kb * 16 + (lane & 3) * 2;
    int g    = lane >> 2;
    __half h[16];
    #pragma unroll
    for (int nb = 0; nb < 4; ++nb) {
        int j = jt * 32 + nb * 8 + g;
        h[nb * 4 + 0] = __float2half(W[(size_t)(k0    ) * N_NEURON + j]);
        h[nb * 4 + 1] = __float2half(W[(size_t)(k0 + 1) * N_NEURON + j]);
        h[nb * 4 + 2] = __float2half(W[(size_t)(k0 + 8) * N_NEURON + j]);
        h[nb * 4 + 3] = __float2half(W[(size_t)(k0 + 9) * N_NEURON + j]);
    }
    uint4* dst = (uint4*)(g_W16 + (size_t)idx * 16);
    dst[0] = ((const uint4*)h)[0];
    dst[1] = ((const uint4*)h)[1];
}

// ---------------- state init: rates0 = relu(ff[:,0] + rec0) ------------------
__global__ void init_state(const float* __restrict__ ff, const float* __restrict__ rec0) {
    int i = blockIdx.x * blockDim.x + threadIdx.x;
    if (i >= N_BATCH * N_NEURON) return;
    int b = i >> 12;
    int j = i & (N_NEURON - 1);
    float r0 = rec0[i];
    float f  = ff[(size_t)b * N_STEPS * N_NEURON + j];
    float rate = fmaxf(f + r0, 0.0f);
    g_rates[i] = rate;
    g_rec[i]   = r0;
    g_acc[i]   = 0.0f;
    int kb = j >> 4, kk = j & 15, rb = b >> 4, g = b & 7;
    int reg  = ((b >> 3) & 1) | ((kk >> 3) << 1);
    int lane = (g << 2) | ((kk & 7) >> 1);
    g_r16[0][(((size_t)(kb * 2 + rb) * 32 + lane) << 3) + (reg << 1) + (kk & 1)] =
        __float2half(rate);
}

// ---------------- fused step: all-LDG fragment GEMM (N=64/CTA) + dynamics -----
__device__ __forceinline__ void mma_16816(float c[4], const uint4& a, uint32_t b0, uint32_t b1) {
    asm volatile("mma.sync.aligned.m16n8k16.row.col.f32.f16.f16.f32 "
        "{%0,%1,%2,%3}, {%4,%5,%6,%7}, {%8,%9}, {%0,%1,%2,%3};\n"
        : "+f"(c[0]), "+f"(c[1]), "+f"(c[2]), "+f"(c[3])
        : "r"(a.x), "r"(a.y), "r"(a.z), "r"(a.w), "r"(b0), "r"(b1));
}

#define SMEM_RED_BYTES (8 * 32 * 64 * 4)   // 64 KB

__global__ void __launch_bounds__(256, 1) step_kernel(
    const float* __restrict__ ff, float* __restrict__ out, int t)
{
    extern __shared__ float red[];          // [8 warps][32 b][64 n]

    const int tid  = threadIdx.x;
    const int warp = tid >> 5;              // k-slice [warp*512, +512)
    const int lane = tid & 31;
    const int j0   = blockIdx.x * 64;
    const int cur  = t & 1, nxt = cur ^ 1;

    const uint4* __restrict__ gA  = (const uint4*)g_r16[cur];
    const uint4* __restrict__ gB0 = (const uint4*)g_W16 + (size_t)(blockIdx.x * 2    ) * 256 * 64;
    const uint4* __restrict__ gB1 = (const uint4*)g_W16 + (size_t)(blockIdx.x * 2 + 1) * 256 * 64;
    // entry (kb,lane) = 2 consecutive uint4 at [(kb*32+lane)*2]

    // epilogue coords + ff prefetch (thread owns (bb, 8 consecutive j))
    const int bb = tid >> 3;
    const int jl = (tid & 7) * 8;
    const int j  = j0 + jl;
    const float4 ffa = *(const float4*)&ff[((size_t)bb * N_STEPS + t) * N_NEURON + j];
    const float4 ffb = *(const float4*)&ff[((size_t)bb * N_STEPS + t) * N_NEURON + j + 4];

    float c[2][8][4];
    #pragma unroll
    for (int rb = 0; rb < 2; ++rb)
        #pragma unroll
        for (int nb = 0; nb < 8; ++nb)
            #pragma unroll
            for (int i = 0; i < 4; ++i) c[rb][nb][i] = 0.f;

    const int kb0 = warp * 32;

    uint4 A0[3], A1[3], Bq[3][4];
    #pragma unroll
    for (int p = 0; p < 3; ++p) {
        int kb = kb0 + p;
        A0[p]    = __ldg(&gA[(kb * 2 + 0) * 32 + lane]);
        A1[p]    = __ldg(&gA[(kb * 2 + 1) * 32 + lane]);
        Bq[p][0] = __ldg(&gB0[(kb * 32 + lane) * 2 + 0]);
        Bq[p][1] = __ldg(&gB0[(kb * 32 + lane) * 2 + 1]);
        Bq[p][2] = __ldg(&gB1[(kb * 32 + lane) * 2 + 0]);
        Bq[p][3] = __ldg(&gB1[(kb * 32 + lane) * 2 + 1]);
    }

    #pragma unroll
    for (int i = 0; i < 32; ++i) {
        const int s = i % 3;
        #pragma unroll
        for (int q = 0; q < 4; ++q) {
            mma_16816(c[0][q * 2    ], A0[s], Bq[s][q].x, Bq[s][q].y);
            mma_16816(c[0][q * 2 + 1], A0[s], Bq[s][q].z, Bq[s][q].w);
            mma_16816(c[1][q * 2    ], A1[s], Bq[s][q].x, Bq[s][q].y);
            mma_16816(c[1][q * 2 + 1], A1[s], Bq[s][q].z, Bq[s][q].w);
        }
        if (i + 3 < 32) {
            int kb = kb0 + i + 3;
            A0[s]    = __ldg(&gA[(kb * 2 + 0) * 32 + lane]);
            A1[s]    = __ldg(&gA[(kb * 2 + 1) * 32 + lane]);
            Bq[s][0] = __ldg(&gB0[(kb * 32 + lane) * 2 + 0]);
            Bq[s][1] = __ldg(&gB0[(kb * 32 + lane) * 2 + 1]);
            Bq[s][2] = __ldg(&gB1[(kb * 32 + lane) * 2 + 0]);
            Bq[s][3] = __ldg(&gB1[(kb * 32 + lane) * 2 + 1]);
        }
    }

    // ---- cross-warp k-reduction through smem (single barrier) ----
    float* myred = red + warp * (32 * 64);
    #pragma unroll
    for (int rb = 0; rb < 2; ++rb)
        #pragma unroll
        for (int nb = 0; nb < 8; ++nb)
            #pragma unroll
            for (int i = 0; i < 4; ++i) {
                int m = rb * 16 + (lane >> 2) + ((i >= 2) ? 8 : 0);
                int n = nb * 8 + (lane & 3) * 2 + (i & 1);
                myred[m * 64 + n] = c[rb][nb][i];
            }
    __syncthreads();

    // ---- fused dynamics + window accumulation ----
    const float E_SYN  = 0.95122942450071403f;
    const float DT_SYN = 0.05f;
    const float E_TAU  = 0.90483741803595957f;
    const float DT_TAU = 0.1f;

    const bool do_acc = (t >= 90);
    const bool do_rec = (t >= 100) && (((t - 100) % 10) == 0);
    const int  w      = (t - 100) / 10;

    const size_t idx = (size_t)bb * N_NEURON + j;

    float h[8] = {0.f,0.f,0.f,0.f,0.f,0.f,0.f,0.f};
    #pragma unroll
    for (int ww = 0; ww < 8; ++ww) {
        const float* r = red + ww * (32 * 64) + bb * 64 + jl;
        float4 p = *(const float4*)r;
        float4 q = *(const float4*)(r + 4);
        h[0] += p.x; h[1] += p.y; h[2] += p.z; h[3] += p.w;
        h[4] += q.x; h[5] += q.y; h[6] += q.z; h[7] += q.w;
    }

    float4 rc0 = *(const float4*)&g_rec[idx];
    float4 rc1 = *(const float4*)&g_rec[idx + 4];
    float4 rt0 = *(const float4*)&g_rates[idx];
    float4 rt1 = *(const float4*)&g_rates[idx + 4];

    float rc[8] = {rc0.x, rc0.y, rc0.z, rc0.w, rc1.x, rc1.y, rc1.z, rc1.w};
    float rt[8] = {rt0.x, rt0.y, rt0.z, rt0.w, rt1.x, rt1.y, rt1.z, rt1.w};
    float fv[8] = {ffa.x, ffa.y, ffa.z, ffa.w, ffb.x, ffb.y, ffb.z, ffb.w};
    #pragma unroll
    for (int x = 0; x < 8; ++x) {
        rc[x] = rc[x] * E_SYN + h[x] * DT_SYN;
        float nl = fmaxf(fv[x] + rc[x], 0.0f);
        rt[x] = rt[x] * E_TAU + nl * DT_TAU;
    }
    *(float4*)&g_rec[idx]       = make_float4(rc[0], rc[1], rc[2], rc[3]);
    *(float4*)&g_rec[idx + 4]   = make_float4(rc[4], rc[5], rc[6], rc[7]);
    *(float4*)&g_rates[idx]     = make_float4(rt[0], rt[1], rt[2], rt[3]);
    *(float4*)&g_rates[idx + 4] = make_float4(rt[4], rt[5], rt[6], rt[7]);

    // next-step rates in A-fragment layout (two groups of 4 consecutive j)
    {
        __half2* base = (__half2*)g_r16[nxt];
        int rb = bb >> 4, g = bb & 7;
        #pragma unroll
        for (int grp = 0; grp < 2; ++grp) {
            int j4 = j + grp * 4;
            int kb = j4 >> 4, kk = j4 & 15;
            int reg   = ((bb >> 3) & 1) | ((kk >> 3) << 1);
            int lane0 = (g << 2) | ((kk & 7) >> 1);
            base[((size_t)(kb * 2 + rb) * 32 + lane0    ) * 4 + reg] =
                __floats2half2_rn(rt[grp * 4 + 0], rt[grp * 4 + 1]);
            base[((size_t)(kb * 2 + rb) * 32 + lane0 + 1) * 4 + reg] =
                __floats2half2_rn(rt[grp * 4 + 2], rt[grp * 4 + 3]);
        }
    }

    if (do_acc) {
        float4 a0 = *(const float4*)&g_acc[idx];
        float4 a1 = *(const float4*)&g_acc[idx + 4];
        float av[8] = {a0.x + rt[0], a0.y + rt[1], a0.z + rt[2], a0.w + rt[3],
                       a1.x + rt[4], a1.y + rt[5], a1.z + rt[6], a1.w + rt[7]};
        if (do_rec) {
            float* o = &out[((size_t)bb * 20 + w) * N_NEURON + j];
            *(float4*)o       = make_float4(av[0] * 0.1f, av[1] * 0.1f, av[2] * 0.1f, av[3] * 0.1f);
            *(float4*)(o + 4) = make_float4(av[4] * 0.1f, av[5] * 0.1f, av[6] * 0.1f, av[7] * 0.1f);
            #pragma unroll
            for (int x = 0; x < 8; ++x) av[x] = 0.f;
        }
        *(float4*)&g_acc[idx]     = make_float4(av[0], av[1], av[2], av[3]);
        *(float4*)&g_acc[idx + 4] = make_float4(av[4], av[5], av[6], av[7]);
    }
}

// ---------------- launch ------------------------------------------------------
extern "C" void kernel_launch(void* const* d_in, const int* in_sizes, int n_in,
                              void* d_out, int out_size) {
    const float* W    = (const float*)d_in[0];   // Wab_T [4096,4096] f32
    const float* ff   = (const float*)d_in[1];   // ff_input [32,300,4096] f32
    const float* rec0 = (const float*)d_in[2];   // rec0 [32,4096] f32
    float* out = (float*)d_out;                  // [32,20,4096] f32

    cudaFuncSetAttribute(step_kernel, cudaFuncAttributeMaxDynamicSharedMemorySize, SMEM_RED_BYTES);

    convert_w<<<(128 * 256 * 32 + 255) / 256, 256>>>(W);
    init_state<<<(N_BATCH * N_NEURON + 255) / 256, 256>>>(ff, rec0);
    for (int t = 0; t < N_STEPS; ++t)
        step_kernel<<<N_NEURON / 64, 256, SMEM_RED_BYTES>>>(ff, out, t);
}

// round 5
// speedup vs baseline: 1.0598x; 1.0598x over previous
#include <cuda_runtime.h>
#include <cuda_fp16.h>
#include <cstdint>

#define N_NEURON 4096
#define N_BATCH  32
#define N_STEPS  300
#define CLUSTER  4

// ---------------- device scratch (allocation-free rule: __device__ globals) ----
// W packed in per-lane MMA B-fragment layout, per 32-col tile (see convert_w).
__device__ __align__(256) __half g_W16[(size_t)N_NEURON * N_NEURON];
// rates in per-lane MMA A-fragment layout (ping-pong):
//   entry (kb, rb, lane) = 8 halves (16 B) = a0..a3 of the m16k16 A fragment
__device__ __align__(256) __half g_r16[2][N_BATCH * N_NEURON];
__device__ float g_rates[N_BATCH * N_NEURON];
__device__ float g_rec[N_BATCH * N_NEURON];
__device__ float g_acc[N_BATCH * N_NEURON];

// ---------------- W fp32 -> fp16 fragment pack (once per replay) --------------
__global__ void convert_w(const float* __restrict__ W) {
    int idx = blockIdx.x * blockDim.x + threadIdx.x;
    if (idx >= 128 * 256 * 32) return;
    int lane = idx & 31;
    int kb   = (idx >> 5) & 255;
    int jt   = idx >> 13;
    int k0   = kb * 16 + (lane & 3) * 2;
    int g    = lane >> 2;
    __half h[16];
    #pragma unroll
    for (int nb = 0; nb < 4; ++nb) {
        int j = jt * 32 + nb * 8 + g;
        h[nb * 4 + 0] = __float2half(W[(size_t)(k0    ) * N_NEURON + j]);
        h[nb * 4 + 1] = __float2half(W[(size_t)(k0 + 1) * N_NEURON + j]);
        h[nb * 4 + 2] = __float2half(W[(size_t)(k0 + 8) * N_NEURON + j]);
        h[nb * 4 + 3] = __float2half(W[(size_t)(k0 + 9) * N_NEURON + j]);
    }
    uint4* dst = (uint4*)(g_W16 + (size_t)idx * 16);
    dst[0] = ((const uint4*)h)[0];
    dst[1] = ((const uint4*)h)[1];
}

// ---------------- state init: rates0 = relu(ff[:,0] + rec0) ------------------
__global__ void init_state(const float* __restrict__ ff, const float* __restrict__ rec0) {
    int i = blockIdx.x * blockDim.x + threadIdx.x;
    if (i >= N_BATCH * N_NEURON) return;
    int b = i >> 12;
    int j = i & (N_NEURON - 1);
    float r0 = rec0[i];
    float f  = ff[(size_t)b * N_STEPS * N_NEURON + j];
    float rate = fmaxf(f + r0, 0.0f);
    g_rates[i] = rate;
    g_rec[i]   = r0;
    g_acc[i]   = 0.0f;
    int kb = j >> 4, kk = j & 15, rb = b >> 4, g = b & 7;
    int reg  = ((b >> 3) & 1) | ((kk >> 3) << 1);
    int lane = (g << 2) | ((kk & 7) >> 1);
    g_r16[0][(((size_t)(kb * 2 + rb) * 32 + lane) << 3) + (reg << 1) + (kk & 1)] =
        __float2half(rate);
}

// ---------------- fused step ---------------------------------------------------
__device__ __forceinline__ void mma_16816(float c[4], const uint4& a, uint32_t b0, uint32_t b1) {
    asm volatile("mma.sync.aligned.m16n8k16.row.col.f32.f16.f16.f32 "
        "{%0,%1,%2,%3}, {%4,%5,%6,%7}, {%8,%9}, {%0,%1,%2,%3};\n"
        : "+f"(c[0]), "+f"(c[1]), "+f"(c[2]), "+f"(c[3])
        : "r"(a.x), "r"(a.y), "r"(a.z), "r"(a.w), "r"(b0), "r"(b1));
}

#define A_HALF_BYTES   (128 * 1024)            // half of the rates array (k-half)
#define A_SLICE_BYTES  (A_HALF_BYTES / CLUSTER) // 32 KB per CTA per round
#define RED_OFF        A_HALF_BYTES
#define RED_BYTES      (8 * 32 * 32 * 4)        // 32 KB
#define MBAR_OFF       (RED_OFF + RED_BYTES)
#define SMEM_TOTAL     (MBAR_OFF + 64)

__global__ void __launch_bounds__(256, 1) __cluster_dims__(CLUSTER, 1, 1)
step_kernel(const float* __restrict__ ff, float* __restrict__ out, int t)
{
    extern __shared__ __align__(16) char sm[];
    float* red = (float*)(sm + RED_OFF);

    const int tid  = threadIdx.x;
    const int warp = tid >> 5;
    const int lane = tid & 31;
    const int jt   = blockIdx.x;
    const int j0   = jt * 32;
    const int cur  = t & 1, nxt = cur ^ 1;

    uint32_t smbase;
    asm("{ .reg .u64 tmp; cvta.to.shared.u64 tmp, %1; cvt.u32.u64 %0, tmp; }"
        : "=r"(smbase) : "l"(sm));
    const uint32_t mbar0 = smbase + MBAR_OFF;
    const uint32_t mbar1 = smbase + MBAR_OFF + 8;

    uint32_t rank;
    asm("mov.u32 %0, %%cluster_ctarank;" : "=r"(rank));

    const uint4* __restrict__ gB = (const uint4*)g_W16 + (size_t)jt * 256 * 64;

    // epilogue coords + ff prefetch
    const int bb = tid >> 3;
    const int jl = (tid & 7) * 4;
    const int j  = j0 + jl;
    const float4 ffv = *(const float4*)&ff[((size_t)bb * N_STEPS + t) * N_NEURON + j];

    // --- mbarrier init + cluster handshake (multicast protocol) ---
    if (tid == 0) {
        asm volatile("mbarrier.init.shared.b64 [%0], %1;" :: "r"(mbar0), "r"(1) : "memory");
        asm volatile("mbarrier.init.shared.b64 [%0], %1;" :: "r"(mbar1), "r"(1) : "memory");
    }
    __syncthreads();
    asm volatile("barrier.cluster.arrive.aligned;" ::: "memory");
    asm volatile("barrier.cluster.wait.aligned;"   ::: "memory");

    // --- round 0: cooperative multicast of rates k-half 0 into all 4 CTAs ---
    if (tid == 0) {
        asm volatile("mbarrier.arrive.expect_tx.shared.b64 _, [%0], %1;"
                     :: "r"(mbar0), "r"((uint32_t)A_HALF_BYTES) : "memory");
        asm volatile("mbarrier.arrive.expect_tx.shared.b64 _, [%0], %1;"
                     :: "r"(mbar1), "r"((uint32_t)A_HALF_BYTES) : "memory");
        const char* src = (const char*)g_r16[cur] + rank * A_SLICE_BYTES;
        asm volatile(
            "cp.async.bulk.shared::cluster.global.mbarrier::complete_tx::bytes.multicast::cluster "
            "[%0], [%1], %2, [%3], %4;"
            :: "r"(smbase + rank * A_SLICE_BYTES), "l"(src),
               "r"((uint32_t)A_SLICE_BYTES), "r"(mbar0), "h"((uint16_t)0xF) : "memory");
    }

    float c[2][4][4];
    #pragma unroll
    for (int rb = 0; rb < 2; ++rb)
        #pragma unroll
        for (int nb = 0; nb < 4; ++nb)
            #pragma unroll
            for (int i = 0; i < 4; ++i) c[rb][nb][i] = 0.f;

    // B prefetch ring (global, register-resident), absolute kb order:
    // i in [0,16) -> kb = warp*16+i (half 0); i in [16,32) -> 128 + warp*16 + (i-16)
    uint4 B0[3], B1[3];
    #pragma unroll
    for (int p = 0; p < 3; ++p) {
        int kb = warp * 16 + p;
        B0[p] = __ldg(&gB[(kb * 32 + lane) * 2 + 0]);
        B1[p] = __ldg(&gB[(kb * 32 + lane) * 2 + 1]);
    }

    // wait for A half 0
    {
        uint32_t done;
        asm volatile("{\n\t.reg .pred p;\n\t"
            "mbarrier.try_wait.parity.acquire.cta.shared::cta.b64 p, [%1], %2;\n\t"
            "selp.b32 %0, 1, 0, p;\n\t}"
            : "=r"(done) : "r"(mbar0), "r"(0) : "memory");
        if (!done) {
            asm volatile("{\n\t.reg .pred P1;\n\t"
                "WL0_%=:\n\t"
                "mbarrier.try_wait.parity.acquire.cta.shared::cta.b64 P1, [%0], %1, 0x989680;\n\t"
                "@P1 bra.uni WD0_%=;\n\t"
                "bra.uni WL0_%=;\n\t"
                "WD0_%=:\n\t}" :: "r"(mbar0), "r"(0) : "memory");
        }
    }

    #pragma unroll
    for (int half = 0; half < 2; ++half) {
        if (half == 1) {
            // all cluster CTAs done reading half 0 before overwriting buffers
            asm volatile("barrier.cluster.arrive.aligned;" ::: "memory");
            asm volatile("barrier.cluster.wait.aligned;"   ::: "memory");
            if (tid == 0) {
                const char* src = (const char*)g_r16[cur] + A_HALF_BYTES + rank * A_SLICE_BYTES;
                asm volatile(
                    "cp.async.bulk.shared::cluster.global.mbarrier::complete_tx::bytes.multicast::cluster "
                    "[%0], [%1], %2, [%3], %4;"
                    :: "r"(smbase + rank * A_SLICE_BYTES), "l"(src),
                       "r"((uint32_t)A_SLICE_BYTES), "r"(mbar1), "h"((uint16_t)0xF) : "memory");
            }
            uint32_t done;
            asm volatile("{\n\t.reg .pred p;\n\t"
                "mbarrier.try_wait.parity.acquire.cta.shared::cta.b64 p, [%1], %2;\n\t"
                "selp.b32 %0, 1, 0, p;\n\t}"
                : "=r"(done) : "r"(mbar1), "r"(0) : "memory");
            if (!done) {
                asm volatile("{\n\t.reg .pred P1;\n\t"
                    "WL1_%=:\n\t"
                    "mbarrier.try_wait.parity.acquire.cta.shared::cta.b64 P1, [%0], %1, 0x989680;\n\t"
                    "@P1 bra.uni WD1_%=;\n\t"
                    "bra.uni WL1_%=;\n\t"
                    "WD1_%=:\n\t}" :: "r"(mbar1), "r"(0) : "memory");
            }
        }

        #pragma unroll
        for (int i = 0; i < 16; ++i) {
            const int it = half * 16 + i;           // global iteration index
            const int s  = it % 3;
            const int kb_local = warp * 16 + i;     // kb within this half

            // A fragments from local smem (multicast-delivered), conflict-free
            uint4 A0, A1;
            {
                uint32_t a0 = smbase + (uint32_t)(((kb_local * 2 + 0) * 32 + lane) * 16);
                uint32_t a1 = smbase + (uint32_t)(((kb_local * 2 + 1) * 32 + lane) * 16);
                asm volatile("ld.shared.v4.u32 {%0,%1,%2,%3}, [%4];"
                    : "=r"(A0.x), "=r"(A0.y), "=r"(A0.z), "=r"(A0.w) : "r"(a0));
                asm volatile("ld.shared.v4.u32 {%0,%1,%2,%3}, [%4];"
                    : "=r"(A1.x), "=r"(A1.y), "=r"(A1.z), "=r"(A1.w) : "r"(a1));
            }

            mma_16816(c[0][0], A0, B0[s].x, B0[s].y);
            mma_16816(c[0][1], A0, B0[s].z, B0[s].w);
            mma_16816(c[0][2], A0, B1[s].x, B1[s].y);
            mma_16816(c[0][3], A0, B1[s].z, B1[s].w);
            mma_16816(c[1][0], A1, B0[s].x, B0[s].y);
            mma_16816(c[1][1], A1, B0[s].z, B0[s].w);
            mma_16816(c[1][2], A1, B1[s].x, B1[s].y);
            mma_16816(c[1][3], A1, B1[s].z, B1[s].w);

            if (it + 3 < 32) {
                int nkb = (it + 3 < 16) ? (warp * 16 + it + 3)
                                        : (128 + warp * 16 + (it + 3 - 16));
                B0[s] = __ldg(&gB[(nkb * 32 + lane) * 2 + 0]);
                B1[s] = __ldg(&gB[(nkb * 32 + lane) * 2 + 1]);
            }
        }
    }

    // ---- cross-warp k-reduction through smem ----
    __syncthreads();    // all warps done reading A smem isn't needed; red is separate region
    float* myred = red + warp * (32 * 32);
    #pragma unroll
    for (int rb = 0; rb < 2; ++rb)
        #pragma unroll
        for (int nb = 0; nb < 4; ++nb)
            #pragma unroll
            for (int i = 0; i < 4; ++i) {
                int m = rb * 16 + (lane >> 2) + ((i >= 2) ? 8 : 0);
                int n = nb * 8 + (lane & 3) * 2 + (i & 1);
                myred[m * 32 + n] = c[rb][nb][i];
            }
    __syncthreads();

    // ---- fused dynamics + window accumulation ----
    const float E_SYN  = 0.95122942450071403f;
    const float DT_SYN = 0.05f;
    const float E_TAU  = 0.90483741803595957f;
    const float DT_TAU = 0.1f;

    const bool do_acc = (t >= 90);
    const bool do_rec = (t >= 100) && (((t - 100) % 10) == 0);
    const int  w      = (t - 100) / 10;

    const size_t idx = (size_t)bb * N_NEURON + j;

    float h[4] = {0.f, 0.f, 0.f, 0.f};
    #pragma unroll
    for (int ww = 0; ww < 8; ++ww) {
        float4 p = *(const float4*)&red[ww * (32 * 32) + bb * 32 + jl];
        h[0] += p.x; h[1] += p.y; h[2] += p.z; h[3] += p.w;
    }

    float4 rec4  = *(const float4*)&g_rec[idx];
    float4 rate4 = *(const float4*)&g_rates[idx];

    float rc[4] = {rec4.x, rec4.y, rec4.z, rec4.w};
    float rt[4] = {rate4.x, rate4.y, rate4.z, rate4.w};
    float fv[4] = {ffv.x, ffv.y, ffv.z, ffv.w};
    #pragma unroll
    for (int x = 0; x < 4; ++x) {
        rc[x] = rc[x] * E_SYN + h[x] * DT_SYN;
        float nl = fmaxf(fv[x] + rc[x], 0.0f);
        rt[x] = rt[x] * E_TAU + nl * DT_TAU;
    }
    *(float4*)&g_rec[idx]   = make_float4(rc[0], rc[1], rc[2], rc[3]);
    *(float4*)&g_rates[idx] = make_float4(rt[0], rt[1], rt[2], rt[3]);

    {
        int kb = j >> 4, kk = j & 15;
        int rb = bb >> 4, g = bb & 7;
        int reg   = ((bb >> 3) & 1) | ((kk >> 3) << 1);
        int lane0 = (g << 2) | ((kk & 7) >> 1);
        __half2* base = (__half2*)g_r16[nxt];
        base[((size_t)(kb * 2 + rb) * 32 + lane0    ) * 4 + reg] = __floats2half2_rn(rt[0], rt[1]);
        base[((size_t)(kb * 2 + rb) * 32 + lane0 + 1) * 4 + reg] = __floats2half2_rn(rt[2], rt[3]);
    }

    if (do_acc) {
        float4 a4 = *(const float4*)&g_acc[idx];
        float av[4] = {a4.x + rt[0], a4.y + rt[1], a4.z + rt[2], a4.w + rt[3]};
        if (do_rec) {
            *(float4*)&out[((size_t)bb * 20 + w) * N_NEURON + j] =
                make_float4(av[0] * 0.1f, av[1] * 0.1f, av[2] * 0.1f, av[3] * 0.1f);
            av[0] = av[1] = av[2] = av[3] = 0.f;
        }
        *(float4*)&g_acc[idx] = make_float4(av[0], av[1], av[2], av[3]);
    }

    // ---- cleanup: inval barriers, cluster-safe exit ----
    __syncthreads();
    if (tid == 0) {
        asm volatile("mbarrier.inval.shared.b64 [%0];" :: "r"(mbar0) : "memory");
        asm volatile("mbarrier.inval.shared.b64 [%0];" :: "r"(mbar1) : "memory");
    }
    asm volatile("barrier.cluster.arrive.aligned;" ::: "memory");
    asm volatile("barrier.cluster.wait.aligned;"   ::: "memory");
}

// ---------------- launch ------------------------------------------------------
extern "C" void kernel_launch(void* const* d_in, const int* in_sizes, int n_in,
                              void* d_out, int out_size) {
    const float* W    = (const float*)d_in[0];   // Wab_T [4096,4096] f32
    const float* ff   = (const float*)d_in[1];   // ff_input [32,300,4096] f32
    const float* rec0 = (const float*)d_in[2];   // rec0 [32,4096] f32
    float* out = (float*)d_out;                  // [32,20,4096] f32

    cudaFuncSetAttribute(step_kernel, cudaFuncAttributeMaxDynamicSharedMemorySize, SMEM_TOTAL);

    convert_w<<<(128 * 256 * 32 + 255) / 256, 256>>>(W);
    init_state<<<(N_BATCH * N_NEURON + 255) / 256, 256>>>(ff, rec0);
    for (int t = 0; t < N_STEPS; ++t)
        step_kernel<<<N_NEURON / 32, 256, SMEM_TOTAL>>>(ff, out, t);
}

// round 6
// speedup vs baseline: 1.5950x; 1.5050x over previous
#include <cuda_runtime.h>
#include <cuda_fp16.h>
#include <cstdint>

#define N_NEURON 4096
#define N_BATCH  32
#define N_STEPS  300
#define NCTA     128

// ---------------- device scratch (allocation-free rule: __device__ globals) ----
__device__ __align__(256) __half g_W16[(size_t)N_NEURON * N_NEURON];
__device__ __align__(256) __half g_r16[2][N_BATCH * N_NEURON];
__device__ unsigned g_cnt;
__device__ unsigned g_gen;

// ---------------- W fp32 -> fp16 fragment pack (once per replay) --------------
__global__ void convert_w(const float* __restrict__ W) {
    int idx = blockIdx.x * blockDim.x + threadIdx.x;
    if (idx >= 128 * 256 * 32) return;
    int lane = idx & 31;
    int kb   = (idx >> 5) & 255;
    int jt   = idx >> 13;
    int k0   = kb * 16 + (lane & 3) * 2;
    int g    = lane >> 2;
    __half h[16];
    #pragma unroll
    for (int nb = 0; nb < 4; ++nb) {
        int j = jt * 32 + nb * 8 + g;
        h[nb * 4 + 0] = __float2half(W[(size_t)(k0    ) * N_NEURON + j]);
        h[nb * 4 + 1] = __float2half(W[(size_t)(k0 + 1) * N_NEURON + j]);
        h[nb * 4 + 2] = __float2half(W[(size_t)(k0 + 8) * N_NEURON + j]);
        h[nb * 4 + 3] = __float2half(W[(size_t)(k0 + 9) * N_NEURON + j]);
    }
    uint4* dst = (uint4*)(g_W16 + (size_t)idx * 16);
    dst[0] = ((const uint4*)h)[0];
    dst[1] = ((const uint4*)h)[1];
}

// ---------------- smem layout ---------------------------------------------------
#define WC_KB        192
#define PLANE_BYTES  (WC_KB * 512)
#define RED_OFF      (2 * PLANE_BYTES)
#define RED_BYTES    (8 * 32 * 32 * 4)
#define SMEM_TOTAL   (RED_OFF + RED_BYTES)   // 229376 B = 224 KB

__device__ __forceinline__ unsigned ld_acq(unsigned* p) {
    unsigned v;
    asm volatile("ld.acquire.gpu.global.u32 %0, [%1];" : "=r"(v) : "l"(p) : "memory");
    return v;
}

__device__ __forceinline__ void grid_barrier(int tid, unsigned target) {
    __syncthreads();
    if (tid == 0) {
        __threadfence();
        unsigned arr = atomicAdd(&g_cnt, 1);
        if (arr == NCTA - 1) {
            atomicExch(&g_cnt, 0);
            __threadfence();
            atomicExch(&g_gen, target);
        } else {
            while (ld_acq(&g_gen) != target) {}
        }
    }
    __syncthreads();
}

__device__ __forceinline__ void lds128(uint4& d, uint32_t addr) {
    asm volatile("ld.shared.v4.u32 {%0,%1,%2,%3}, [%4];"
        : "=r"(d.x), "=r"(d.y), "=r"(d.z), "=r"(d.w) : "r"(addr));
}
__device__ __forceinline__ void stcg32(void* p, uint32_t v) {
    asm volatile("st.global.cg.u32 [%0], %1;" :: "l"(p), "r"(v) : "memory");
}
__device__ __forceinline__ uint32_t h2u(float a, float b) {
    __half2 h = __floats2half2_rn(a, b);
    return *(uint32_t*)&h;
}
__device__ __forceinline__ void mma_16816(float c[4], const uint4& a, uint32_t b0, uint32_t b1) {
    asm volatile("mma.sync.aligned.m16n8k16.row.col.f32.f16.f16.f32 "
        "{%0,%1,%2,%3}, {%4,%5,%6,%7}, {%8,%9}, {%0,%1,%2,%3};\n"
        : "+f"(c[0]), "+f"(c[1]), "+f"(c[2]), "+f"(c[3])
        : "r"(a.x), "r"(a.y), "r"(a.z), "r"(a.w), "r"(b0), "r"(b1));
}

// ---------------- persistent fused simulation kernel ---------------------------
__global__ void __launch_bounds__(256, 1) persist_kernel(
    const float* __restrict__ ff, const float* __restrict__ rec0,
    float* __restrict__ out)
{
    extern __shared__ __align__(16) char sm[];
    float* red = (float*)(sm + RED_OFF);

    const int tid  = threadIdx.x;
    const int warp = tid >> 5;
    const int lane = tid & 31;
    const int jt   = blockIdx.x;
    const int j0   = jt * 32;

    uint32_t smbase;
    asm("{ .reg .u64 t0; cvta.to.shared.u64 t0, %1; cvt.u32.u64 %0, t0; }"
        : "=r"(smbase) : "l"(sm));

    const uint4* __restrict__ gB = (const uint4*)g_W16 + (size_t)jt * 256 * 64;

    const int bb = tid >> 3;
    const int jl = (tid & 7) * 4;
    const int j  = j0 + jl;

    unsigned tgt = ld_acq(&g_gen);   // relative base: replay-safe

    // ---- prologue: cache first 192 kb-entries of W stripe into two smem planes
    {
        const char* src = (const char*)gB;
        for (int s = tid; s < WC_KB * 32; s += 256) {
            uint32_t d0 = smbase + s * 16;
            uint32_t d1 = smbase + PLANE_BYTES + s * 16;
            const char* g0 = src + (size_t)s * 32;
            asm volatile("cp.async.cg.shared.global [%0], [%1], 16;" :: "r"(d0), "l"(g0));
            asm volatile("cp.async.cg.shared.global [%0], [%1], 16;" :: "r"(d1), "l"(g0 + 16));
        }
        asm volatile("cp.async.commit_group;");
        asm volatile("cp.async.wait_group 0;");
    }

    // ---- state init in registers ----
    float rc[4], rt[4], av[4];
    {
        const size_t idx = (size_t)bb * N_NEURON + j;
        float4 r0 = *(const float4*)&rec0[idx];
        float4 f0 = __ldg((const float4*)&ff[((size_t)bb * N_STEPS) * N_NEURON + j]);
        rc[0] = r0.x; rc[1] = r0.y; rc[2] = r0.z; rc[3] = r0.w;
        rt[0] = fmaxf(f0.x + r0.x, 0.f); rt[1] = fmaxf(f0.y + r0.y, 0.f);
        rt[2] = fmaxf(f0.z + r0.z, 0.f); rt[3] = fmaxf(f0.w + r0.w, 0.f);
        av[0] = av[1] = av[2] = av[3] = 0.f;
        int kb = j >> 4, kk = j & 15;
        int rb2 = bb >> 4, g = bb & 7;
        int reg   = ((bb >> 3) & 1) | ((kk >> 3) << 1);
        int lane0 = (g << 2) | ((kk & 7) >> 1);
        __half2* basep = (__half2*)g_r16[0];
        stcg32(&basep[((size_t)(kb * 2 + rb2) * 32 + lane0    ) * 4 + reg], h2u(rt[0], rt[1]));
        stcg32(&basep[((size_t)(kb * 2 + rb2) * 32 + lane0 + 1) * 4 + reg], h2u(rt[2], rt[3]));
    }
    grid_barrier(tid, ++tgt);

    const float E_SYN  = 0.95122942450071403f;
    const float DT_SYN = 0.05f;
    const float E_TAU  = 0.90483741803595957f;
    const float DT_TAU = 0.1f;

    for (int t = 0; t < N_STEPS; ++t) {
        const int cur = t & 1, nxt = cur ^ 1;
        const uint4* __restrict__ gA = (const uint4*)g_r16[cur];

        const float4 ffv = __ldg((const float4*)&ff[((size_t)bb * N_STEPS + t) * N_NEURON + j]);

        float c[2][4][4];
        #pragma unroll
        for (int rb = 0; rb < 2; ++rb)
            #pragma unroll
            for (int nb = 0; nb < 4; ++nb)
                #pragma unroll
                for (int i = 0; i < 4; ++i) c[rb][nb][i] = 0.f;

        uint4 Ar0[3], Ar1[3], Bg0[3], Bg1[3], Bs0[2], Bs1[2];
        #pragma unroll
        for (int p = 0; p < 3; ++p) {
            int ka = warp * 24 + p;
            Ar0[p] = __ldcg(&gA[(ka * 2 + 0) * 32 + lane]);
            Ar1[p] = __ldcg(&gA[(ka * 2 + 1) * 32 + lane]);
            int kg = 192 + warp * 8 + p;
            Bg0[p] = __ldg(&gB[(kg * 32 + lane) * 2 + 0]);
            Bg1[p] = __ldg(&gB[(kg * 32 + lane) * 2 + 1]);
        }
        {
            uint32_t off = (uint32_t)((warp * 24) * 512 + lane * 16);
            lds128(Bs0[0], smbase + off);
            lds128(Bs1[0], smbase + PLANE_BYTES + off);
        }

        #pragma unroll
        for (int i = 0; i < 32; ++i) {
            const int r  = i & 3;
            const int g4 = i >> 2;
            uint4 A0 = Ar0[i % 3], A1 = Ar1[i % 3];
            uint4 B0, B1;
            if (r < 3) {
                const int smi = g4 * 3 + r;
                B0 = Bs0[smi & 1]; B1 = Bs1[smi & 1];
                if (smi + 1 < 24) {
                    uint32_t off = (uint32_t)((warp * 24 + smi + 1) * 512 + lane * 16);
                    lds128(Bs0[(smi + 1) & 1], smbase + off);
                    lds128(Bs1[(smi + 1) & 1], smbase + PLANE_BYTES + off);
                }
            } else {
                B0 = Bg0[g4 % 3]; B1 = Bg1[g4 % 3];
                if (g4 + 3 < 8) {
                    int kg = 192 + warp * 8 + g4 + 3;
                    Bg0[g4 % 3] = __ldg(&gB[(kg * 32 + lane) * 2 + 0]);
                    Bg1[g4 % 3] = __ldg(&gB[(kg * 32 + lane) * 2 + 1]);
                }
            }

            mma_16816(c[0][0], A0, B0.x, B0.y);
            mma_16816(c[0][1], A0, B0.z, B0.w);
            mma_16816(c[0][2], A0, B1.x, B1.y);
            mma_16816(c[0][3], A0, B1.z, B1.w);
            mma_16816(c[1][0], A1, B0.x, B0.y);
            mma_16816(c[1][1], A1, B0.z, B0.w);
            mma_16816(c[1][2], A1, B1.x, B1.y);
            mma_16816(c[1][3], A1, B1.z, B1.w);

            if (i + 3 < 32) {
                const int ni = i + 3, nr = ni & 3, ng = ni >> 2;
                const int nk = (nr < 3) ? (warp * 24 + ng * 3 + nr) : (192 + warp * 8 + ng);
                Ar0[i % 3] = __ldcg(&gA[(nk * 2 + 0) * 32 + lane]);
                Ar1[i % 3] = __ldcg(&gA[(nk * 2 + 1) * 32 + lane]);
            }
        }

        // ---- cross-warp k-reduction through smem ----
        float* myred = red + warp * (32 * 32);
        #pragma unroll
        for (int rb = 0; rb < 2; ++rb)
            #pragma unroll
            for (int nb = 0; nb < 4; ++nb)
                #pragma unroll
                for (int i = 0; i < 4; ++i) {
                    int m = rb * 16 + (lane >> 2) + ((i >= 2) ? 8 : 0);
                    int n = nb * 8 + (lane & 3) * 2 + (i & 1);
                    myred[m * 32 + n] = c[rb][nb][i];
                }
        __syncthreads();

        float h[4] = {0.f, 0.f, 0.f, 0.f};
        #pragma unroll
        for (int ww = 0; ww < 8; ++ww) {
            float4 p = *(const float4*)&red[ww * (32 * 32) + bb * 32 + jl];
            h[0] += p.x; h[1] += p.y; h[2] += p.z; h[3] += p.w;
        }

        const float fv[4] = {ffv.x, ffv.y, ffv.z, ffv.w};
        #pragma unroll
        for (int x = 0; x < 4; ++x) {
            rc[x] = rc[x] * E_SYN + h[x] * DT_SYN;
            float nl = fmaxf(fv[x] + rc[x], 0.0f);
            rt[x] = rt[x] * E_TAU + nl * DT_TAU;
        }

        {
            int kb = j >> 4, kk = j & 15;
            int rb2 = bb >> 4, g = bb & 7;
            int reg   = ((bb >> 3) & 1) | ((kk >> 3) << 1);
            int lane0 = (g << 2) | ((kk & 7) >> 1);
            __half2* basep = (__half2*)g_r16[nxt];
            stcg32(&basep[((size_t)(kb * 2 + rb2) * 32 + lane0    ) * 4 + reg], h2u(rt[0], rt[1]));
            stcg32(&basep[((size_t)(kb * 2 + rb2) * 32 + lane0 + 1) * 4 + reg], h2u(rt[2], rt[3]));
        }

        if (t >= 90) {
            av[0] += rt[0]; av[1] += rt[1]; av[2] += rt[2]; av[3] += rt[3];
            if (t >= 100 && ((t - 100) % 10) == 0) {
                const int w = (t - 100) / 10;
                *(float4*)&out[((size_t)bb * 20 + w) * N_NEURON + j] =
                    make_float4(av[0] * 0.1f, av[1] * 0.1f, av[2] * 0.1f, av[3] * 0.1f);
                av[0] = av[1] = av[2] = av[3] = 0.f;
            }
        }

        if (t < N_STEPS - 1) grid_barrier(tid, ++tgt);
    }
}

// ---------------- launch ------------------------------------------------------
extern "C" void kernel_launch(void* const* d_in, const int* in_sizes, int n_in,
                              void* d_out, int out_size) {
    const float* W    = (const float*)d_in[0];   // Wab_T [4096,4096] f32
    const float* ff   = (const float*)d_in[1];   // ff_input [32,300,4096] f32
    const float* rec0 = (const float*)d_in[2];   // rec0 [32,4096] f32
    float* out = (float*)d_out;                  // [32,20,4096] f32

    cudaFuncSetAttribute(persist_kernel, cudaFuncAttributeMaxDynamicSharedMemorySize, SMEM_TOTAL);

    convert_w<<<(128 * 256 * 32 + 255) / 256, 256>>>(W);
    persist_kernel<<<NCTA, 256, SMEM_TOTAL>>>(ff, rec0, out);
}